// round 11
// baseline (speedup 1.0000x reference)
#include <cuda_runtime.h>
#include <cstdint>

typedef unsigned long long u64;

// ---------- packed f32x2 helpers ----------
__device__ __forceinline__ u64 pk2(float lo, float hi) {
    u64 r;
    asm("mov.b64 %0, {%1, %2};" : "=l"(r)
        : "r"(__float_as_uint(lo)), "r"(__float_as_uint(hi)));
    return r;
}
__device__ __forceinline__ void upk(u64 a, float& lo, float& hi) {
    unsigned int l_, h_;
    asm("mov.b64 {%0, %1}, %2;" : "=r"(l_), "=r"(h_) : "l"(a));
    lo = __uint_as_float(l_);
    hi = __uint_as_float(h_);
}
__device__ __forceinline__ u64 dfma(u64 a, u64 b, u64 c) {
    u64 d;
    asm("fma.rn.f32x2 %0, %1, %2, %3;" : "=l"(d) : "l"(a), "l"(b), "l"(c));
    return d;
}
__device__ __forceinline__ u64 dmul(u64 a, u64 b) {
    u64 d;
    asm("mul.rn.f32x2 %0, %1, %2;" : "=l"(d) : "l"(a), "l"(b));
    return d;
}
__device__ __forceinline__ u64 dadd(u64 a, u64 b) {
    u64 d;
    asm("add.rn.f32x2 %0, %1, %2;" : "=l"(d) : "l"(a), "l"(b));
    return d;
}
// 2*relu(x) per half, exact: x + |x| (2x folded into pre-halved W2/W3)
__device__ __forceinline__ u64 drelu2(u64 a) {
    return dadd(a, a & 0x7FFFFFFF7FFFFFFFULL);
}
__device__ __forceinline__ uint32_t smem_u32(const void* p) {
    uint32_t a;
    asm("{ .reg .u64 t; cvta.to.shared.u64 t, %1; cvt.u32.u64 %0, t; }"
        : "=r"(a) : "l"(p));
    return a;
}
__device__ __forceinline__ void ldsw2(uint32_t addr, u64& a, u64& b) {
    asm("ld.shared.v2.u64 {%0, %1}, [%2];" : "=l"(a), "=l"(b) : "r"(addr));
}
__device__ __forceinline__ void lds128(uint32_t addr, float4& q) {
    asm("ld.shared.v4.f32 {%0, %1, %2, %3}, [%4];"
        : "=f"(q.x), "=f"(q.y), "=f"(q.z), "=f"(q.w) : "r"(addr));
}
__device__ __forceinline__ void cp16(uint32_t dst, const char* src) {
    asm volatile("cp.async.cg.shared.global [%0], [%1], 16;"
                 :: "r"(dst), "l"(src) : "memory");
}
__device__ __forceinline__ void cp16p(uint32_t dst, const char* src, bool pred) {
    if (pred)
        asm volatile("cp.async.cg.shared.global [%0], [%1], 16;"
                     :: "r"(dst), "l"(src) : "memory");
}
__device__ __forceinline__ void cp_commit() {
    asm volatile("cp.async.commit_group;" ::: "memory");
}
__device__ __forceinline__ void cp_wait1() {
    asm volatile("cp.async.wait_group 1;" ::: "memory");
}

// Smem weights: ONLY layers 2/3 (u64 packed (v,v)):
//  [6j..6j+4] = .5*W2[j,0..4], [6j+5] = b2[j]   (j=0..4)  -> [0..29]
//  [30..34]   = .5*W3[0..4],   [35]   = b3
// Layer-1 weights (w1[15], bb1[5]) live in per-thread registers.
// Dual pair step: TWO packed pairs share every smem weight load.
__device__ __forceinline__ void dual_step(
    u64 axA, u64 ayA, u64 azA,
    u64 axB, u64 ayB, u64 azB,
    u64 npx, u64 npy, u64 npz,
    const u64* w1, const u64* bb1,
    uint32_t swb,
    u64& vx, u64& vy, u64& vz)
{
    u64 dxA = dadd(axA, npx), dyA = dadd(ayA, npy), dzA = dadd(azA, npz);
    u64 dxB = dadd(axB, npx), dyB = dadd(ayB, npy), dzB = dadd(azB, npz);
    u64 d2A = dfma(dxA, dxA, dfma(dyA, dyA, dmul(dzA, dzA)));
    u64 d2B = dfma(dxB, dxB, dfma(dyB, dyB, dmul(dzB, dzB)));
    float a0, a1, b0, b1;
    upk(d2A, a0, a1); upk(d2B, b0, b1);
    float iA0 = rsqrtf(fmaxf(a0, 1e-24f));   // matches v/max(||v||,1e-12)
    float iA1 = rsqrtf(fmaxf(a1, 1e-24f));
    float iB0 = rsqrtf(fmaxf(b0, 1e-24f));
    float iB1 = rsqrtf(fmaxf(b1, 1e-24f));

    // Layer 1 from REGISTERS on unnormalized diffs (overlaps MUFU rsqrt)
    u64 uA0 = dfma(dzA, w1[2],  dfma(dyA, w1[1],  dmul(dxA, w1[0])));
    u64 uB0 = dfma(dzB, w1[2],  dfma(dyB, w1[1],  dmul(dxB, w1[0])));
    u64 uA1 = dfma(dzA, w1[5],  dfma(dyA, w1[4],  dmul(dxA, w1[3])));
    u64 uB1 = dfma(dzB, w1[5],  dfma(dyB, w1[4],  dmul(dxB, w1[3])));
    u64 uA2 = dfma(dzA, w1[8],  dfma(dyA, w1[7],  dmul(dxA, w1[6])));
    u64 uB2 = dfma(dzB, w1[8],  dfma(dyB, w1[7],  dmul(dxB, w1[6])));
    u64 uA3 = dfma(dzA, w1[11], dfma(dyA, w1[10], dmul(dxA, w1[9])));
    u64 uB3 = dfma(dzB, w1[11], dfma(dyB, w1[10], dmul(dxB, w1[9])));
    u64 uA4 = dfma(dzA, w1[14], dfma(dyA, w1[13], dmul(dxA, w1[12])));
    u64 uB4 = dfma(dzB, w1[14], dfma(dyB, w1[13], dmul(dxB, w1[12])));

    u64 invA = pk2(iA0, iA1);
    u64 invB = pk2(iB0, iB1);

    u64 hA0 = drelu2(dfma(uA0, invA, bb1[0])), hB0 = drelu2(dfma(uB0, invB, bb1[0]));
    u64 hA1 = drelu2(dfma(uA1, invA, bb1[1])), hB1 = drelu2(dfma(uB1, invB, bb1[1]));
    u64 hA2 = drelu2(dfma(uA2, invA, bb1[2])), hB2 = drelu2(dfma(uB2, invB, bb1[2]));
    u64 hA3 = drelu2(dfma(uA3, invA, bb1[3])), hB3 = drelu2(dfma(uB3, invB, bb1[3]));
    u64 hA4 = drelu2(dfma(uA4, invA, bb1[4])), hB4 = drelu2(dfma(uB4, invB, bb1[4]));

    // Layer 2 from smem (pre-scaled by 0.5), loads shared A/B
    u64 wa, wb, wc, wd, we, bj;
    u64 gA0, gA1, gA2, gA3, gA4, gB0, gB1, gB2, gB3, gB4;
#define L2ROW(GA, GB, J)                                                     \
    ldsw2(swb + (J) * 48u + 0u,  wa, wb);                                    \
    ldsw2(swb + (J) * 48u + 16u, wc, wd);                                    \
    ldsw2(swb + (J) * 48u + 32u, we, bj);                                    \
    GA = dfma(hA0, wa, bj); GA = dfma(hA1, wb, GA); GA = dfma(hA2, wc, GA);  \
    GA = dfma(hA3, wd, GA); GA = dfma(hA4, we, GA); GA = drelu2(GA);         \
    GB = dfma(hB0, wa, bj); GB = dfma(hB1, wb, GB); GB = dfma(hB2, wc, GB);  \
    GB = dfma(hB3, wd, GB); GB = dfma(hB4, we, GB); GB = drelu2(GB);
    L2ROW(gA0, gB0, 0) L2ROW(gA1, gB1, 1) L2ROW(gA2, gB2, 2)
    L2ROW(gA3, gB3, 3) L2ROW(gA4, gB4, 4)
#undef L2ROW

    // Layer 3 from smem (pre-scaled by 0.5)
    ldsw2(swb + 240u, wa, wb);
    ldsw2(swb + 256u, wc, wd);
    ldsw2(swb + 272u, we, bj);
    u64 wgA = dfma(gA0, wa, bj);
    wgA = dfma(gA1, wb, wgA); wgA = dfma(gA2, wc, wgA);
    wgA = dfma(gA3, wd, wgA); wgA = dfma(gA4, we, wgA);
    u64 wgB = dfma(gB0, wa, bj);
    wgB = dfma(gB1, wb, wgB); wgB = dfma(gB2, wc, wgB);
    wgB = dfma(gB3, wd, wgB); wgB = dfma(gB4, we, wgB);

    // vel += nd * w == d * (inv * w)
    u64 wiA = dmul(wgA, invA);
    u64 wiB = dmul(wgB, invB);
    vx = dfma(dxA, wiA, vx); vy = dfma(dyA, wiA, vy); vz = dfma(dzA, wiA, vz);
    vx = dfma(dxB, wiB, vx); vy = dfma(dyB, wiB, vy); vz = dfma(dzB, wiB, vz);
}

// Persistent blocks, double-buffered block staging (proven L1 fix from R10).
// Tile = 128 points (49152B gmem -> 51200B smem, 400B/pt padded: conflict-free
// LDS.128). 256 threads: warp w covers 16 pts; half l>>4 takes 16 neighbors.
#define TILE_PTS 128
#define PT_B     400u
#define BUF_B    51200u
#define TILE_GB  49152LL

__device__ __forceinline__ void stage_tile_full(uint32_t dstb, const char* gn,
                                                long long t, int tid) {
    long long src = t * TILE_GB;
#pragma unroll
    for (int c = 0; c < 12; c++) {
        int m = tid + 256 * c;
        int pp = m / 24, r = m - pp * 24;
        cp16(dstb + (uint32_t)pp * PT_B + (uint32_t)r * 16u,
             gn + src + (long long)m * 16);
    }
}
__device__ __forceinline__ void stage_tile_pred(uint32_t dstb, const char* gn,
                                                long long t, int tid,
                                                long long nbytes) {
    long long src = t * TILE_GB;
#pragma unroll
    for (int c = 0; c < 12; c++) {
        int m = tid + 256 * c;
        int pp = m / 24, r = m - pp * 24;
        long long off = src + (long long)m * 16;
        cp16p(dstb + (uint32_t)pp * PT_B + (uint32_t)r * 16u,
              gn + off, off + 16 <= nbytes);
    }
}

__global__ void __launch_bounds__(256, 2)
velvec_kernel(const float* __restrict__ pos, const float* __restrict__ nbr,
              const float* __restrict__ W1, const float* __restrict__ b1,
              const float* __restrict__ W2, const float* __restrict__ b2,
              const float* __restrict__ W3, const float* __restrict__ b3,
              float* __restrict__ out, int N, int ntiles)
{
    extern __shared__ char buf[];              // 2 * 51200 B
    __shared__ __align__(16) u64 sw[36];

    int tid = threadIdx.x;

    // L2/L3 weights into smem (pre-scaled by 0.5)
    if (tid < 36) {
        float v;
        if (tid < 30) {
            int j = tid / 6, i = tid - 6 * j;
            v = (i < 5) ? 0.5f * __ldg(W2 + 5 * j + i) : __ldg(b2 + j);
        } else if (tid < 35) {
            v = 0.5f * __ldg(W3 + tid - 30);
        } else {
            v = __ldg(b3);
        }
        unsigned int u = __float_as_uint(v);
        sw[tid] = ((u64)u << 32) | (u64)u;
    }

    // L1 weights into registers (warp-uniform broadcast loads)
    u64 w1[15], bb1[5];
#pragma unroll
    for (int i = 0; i < 15; i++) {
        float v = __ldg(W1 + i);
        unsigned int u = __float_as_uint(v);
        w1[i] = ((u64)u << 32) | (u64)u;
    }
#pragma unroll
    for (int i = 0; i < 5; i++) {
        float v = __ldg(b1 + i);
        unsigned int u = __float_as_uint(v);
        bb1[i] = ((u64)u << 32) | (u64)u;
    }
    __syncthreads();

    uint32_t swb = smem_u32(sw);
    uint32_t bufb = smem_u32(buf);
    const char* gn = (const char*)nbr;
    long long nbytes = (long long)N * 384;

    int w = tid >> 5;
    int l = tid & 31;
    int p = (w & 7) * 16 + (l & 15);     // point in tile
    int half = l >> 4;                    // neighbor half (16 each)

    int G = gridDim.x;
    int full = ntiles - 1;

    // prologue: stage tiles t0, t0+G
    {
        long long t0 = blockIdx.x;
        if (t0 < ntiles) {
            if (t0 < full) stage_tile_full(bufb, gn, t0, tid);
            else           stage_tile_pred(bufb, gn, t0, tid, nbytes);
        }
        cp_commit();
        long long t1 = t0 + G;
        if (t1 < ntiles) {
            if (t1 < full) stage_tile_full(bufb + BUF_B, gn, t1, tid);
            else           stage_tile_pred(bufb + BUF_B, gn, t1, tid, nbytes);
        }
        cp_commit();
    }

    int k = 0;
    for (long long t = blockIdx.x; t < ntiles; t += G, k++) {
        cp_wait1();
        __syncthreads();

        uint32_t myb = bufb + (uint32_t)(k & 1) * BUF_B;
        int n = (int)(t * TILE_PTS) + p;

        float px = 0.f, py = 0.f, pz = 0.f;
        if (n < N) {
            px = __ldg(pos + 3 * n + 0);
            py = __ldg(pos + 3 * n + 1);
            pz = __ldg(pos + 3 * n + 2);
        }
        u64 npx = pk2(-px, -px), npy = pk2(-py, -py), npz = pk2(-pz, -pz);
        u64 vx = 0ULL, vy = 0ULL, vz = 0ULL;

        uint32_t rb = myb + (uint32_t)p * PT_B + (uint32_t)half * 192u;

        // software-pipelined data reads: next gi's LDS issues before the
        // current dual_step so its 29-cyc latency hides under compute.
        float4 q0, q1, q2, r0, r1, r2;
        lds128(rb + 0u,  q0);
        lds128(rb + 16u, q1);
        lds128(rb + 32u, q2);
#pragma unroll 1
        for (int gi = 0; gi < 4; gi++) {
            if (gi < 3) {
                lds128(rb + (gi + 1) * 48u + 0u,  r0);
                lds128(rb + (gi + 1) * 48u + 16u, r1);
                lds128(rb + (gi + 1) * 48u + 32u, r2);
            }
            dual_step(pk2(q0.x, q0.w), pk2(q0.y, q1.x), pk2(q0.z, q1.y),
                      pk2(q1.z, q2.y), pk2(q1.w, q2.z), pk2(q2.x, q2.w),
                      npx, npy, npz, w1, bb1, swb, vx, vy, vz);
            q0 = r0; q1 = r1; q2 = r2;
        }

        float x0, x1, y0, y1, z0, z1;
        upk(vx, x0, x1); upk(vy, y0, y1); upk(vz, z0, z1);
        float fx = x0 + x1, fy = y0 + y1, fz = z0 + z1;
        fx += __shfl_xor_sync(0xFFFFFFFFu, fx, 16);
        fy += __shfl_xor_sync(0xFFFFFFFFu, fy, 16);
        fz += __shfl_xor_sync(0xFFFFFFFFu, fz, 16);

        if (half == 0 && n < N) {
            float d2 = fmaf(fx, fx, fmaf(fy, fy, fz * fz));
            d2 = fmaxf(d2, 1e-24f);
            float r = rsqrtf(d2);
            r = r * fmaf(-0.5f * d2 * r, r, 1.5f);  // one Newton step
            out[3 * n + 0] = fx * r;
            out[3 * n + 1] = fy * r;
            out[3 * n + 2] = fz * r;
        }

        __syncthreads();
        long long t2 = t + 2 * G;
        if (t2 < ntiles) {
            if (t2 < full) stage_tile_full(myb, gn, t2, tid);
            else           stage_tile_pred(myb, gn, t2, tid, nbytes);
        }
        cp_commit();
    }
}

extern "C" void kernel_launch(void* const* d_in, const int* in_sizes, int n_in,
                              void* d_out, int out_size)
{
    const float* pos = (const float*)d_in[0];
    const float* nbr = (const float*)d_in[1];
    const float* W1  = (const float*)d_in[2];
    const float* b1  = (const float*)d_in[3];
    const float* W2  = (const float*)d_in[4];
    const float* b2  = (const float*)d_in[5];
    const float* W3  = (const float*)d_in[6];
    const float* b3  = (const float*)d_in[7];
    float* out = (float*)d_out;

    static bool attr_set = false;
    if (!attr_set) {
        cudaFuncSetAttribute(velvec_kernel,
                             cudaFuncAttributeMaxDynamicSharedMemorySize, 102400);
        attr_set = true;
    }

    int N = in_sizes[0] / 3;            // positions is [N,3]
    int ntiles = (N + TILE_PTS - 1) / TILE_PTS;
    int grid = 296;                     // 2 persistent blocks per SM
    if (grid > ntiles) grid = ntiles;
    velvec_kernel<<<grid, 256, 102400>>>(pos, nbr, W1, b1, W2, b2, W3, b3,
                                         out, N, ntiles);
}

// round 12
// speedup vs baseline: 1.2557x; 1.2557x over previous
#include <cuda_runtime.h>
#include <cstdint>

typedef unsigned long long u64;

// Packed (v,v) pre-scaled weights in the constant bank.
// Layout: [0:15) W1, [15:20) b1, [20:45) 0.5*W2, [45:50) b2, [50:55) 0.5*W3, [55] b3
__constant__ u64 c_w[60];
__device__ u64 g_pack[60];

__global__ void pack_weights_kernel(const float* __restrict__ W1, const float* __restrict__ b1,
                                    const float* __restrict__ W2, const float* __restrict__ b2,
                                    const float* __restrict__ W3, const float* __restrict__ b3)
{
    int i = threadIdx.x;
    if (i >= 60) return;
    float v = 0.0f;
    if      (i < 15) v = W1[i];
    else if (i < 20) v = b1[i - 15];
    else if (i < 45) v = 0.5f * W2[i - 20];
    else if (i < 50) v = b2[i - 45];
    else if (i < 55) v = 0.5f * W3[i - 50];
    else if (i == 55) v = b3[0];
    unsigned int u = __float_as_uint(v);
    g_pack[i] = ((u64)u << 32) | (u64)u;
}

// ---------- packed f32x2 helpers ----------
__device__ __forceinline__ u64 pk2(float lo, float hi) {
    u64 r;
    asm("mov.b64 %0, {%1, %2};" : "=l"(r)
        : "r"(__float_as_uint(lo)), "r"(__float_as_uint(hi)));
    return r;
}
__device__ __forceinline__ void upk(u64 a, float& lo, float& hi) {
    unsigned int l_, h_;
    asm("mov.b64 {%0, %1}, %2;" : "=r"(l_), "=r"(h_) : "l"(a));
    lo = __uint_as_float(l_);
    hi = __uint_as_float(h_);
}
__device__ __forceinline__ u64 dfma(u64 a, u64 b, u64 c) {
    u64 d;
    asm("fma.rn.f32x2 %0, %1, %2, %3;" : "=l"(d) : "l"(a), "l"(b), "l"(c));
    return d;
}
__device__ __forceinline__ u64 dmul(u64 a, u64 b) {
    u64 d;
    asm("mul.rn.f32x2 %0, %1, %2;" : "=l"(d) : "l"(a), "l"(b));
    return d;
}
__device__ __forceinline__ u64 dadd(u64 a, u64 b) {
    u64 d;
    asm("add.rn.f32x2 %0, %1, %2;" : "=l"(d) : "l"(a), "l"(b));
    return d;
}
// 2*relu(x) per half, exact: x + |x| (2x folded into pre-halved W2/W3)
__device__ __forceinline__ u64 drelu2(u64 a) {
    return dadd(a, a & 0x7FFFFFFF7FFFFFFFULL);
}

// One warp = 4 points; 8 lanes per point; each lane loads its own contiguous
// 48B (4 neighbors = 2 packed pairs) and runs ONE dual step. Constants are
// read once per thread (threads are short-lived: no reuse pressure, no
// weight registers). shfl_xor(1,2,4) reduces the 8-lane cluster.
__global__ void __launch_bounds__(128)
velvec_kernel(const float* __restrict__ pos, const float* __restrict__ nbr,
              float* __restrict__ out, int N)
{
    int gw = (blockIdx.x * blockDim.x + threadIdx.x) >> 5;  // global warp id
    int l = threadIdx.x & 31;
    int p = l >> 3;            // point within warp's group of 4
    int j = l & 7;             // 48B slice within the point's 384B row
    int n = gw * 4 + p;        // global point index
    bool act = (n < N);

    // ---- load this lane's 4 neighbors (3x LDG.128, contiguous 48B) ----
    float4 q0 = make_float4(0.f, 0.f, 0.f, 0.f), q1 = q0, q2 = q0;
    if (act) {
        const float4* bp = reinterpret_cast<const float4*>(
            (const char*)nbr + (size_t)n * 384 + (size_t)j * 48);
        q0 = __ldg(bp + 0);    // x0 y0 z0 x1
        q1 = __ldg(bp + 1);    // y1 z1 x2 y2
        q2 = __ldg(bp + 2);    // z2 x3 y3 z3
    }

    float px = 0.f, py = 0.f, pz = 0.f;
    if (act) {
        px = __ldg(pos + 3 * n + 0);
        py = __ldg(pos + 3 * n + 1);
        pz = __ldg(pos + 3 * n + 2);
    }
    u64 npx = pk2(-px, -px), npy = pk2(-py, -py), npz = pk2(-pz, -pz);

    // pair A = neighbors 0,1 of the slice; pair B = neighbors 2,3
    u64 axA = pk2(q0.x, q0.w), ayA = pk2(q0.y, q1.x), azA = pk2(q0.z, q1.y);
    u64 axB = pk2(q1.z, q2.y), ayB = pk2(q1.w, q2.z), azB = pk2(q2.x, q2.w);

    u64 dxA = dadd(axA, npx), dyA = dadd(ayA, npy), dzA = dadd(azA, npz);
    u64 dxB = dadd(axB, npx), dyB = dadd(ayB, npy), dzB = dadd(azB, npz);
    u64 d2A = dfma(dxA, dxA, dfma(dyA, dyA, dmul(dzA, dzA)));
    u64 d2B = dfma(dxB, dxB, dfma(dyB, dyB, dmul(dzB, dzB)));
    float a0, a1, b0, b1;
    upk(d2A, a0, a1); upk(d2B, b0, b1);
    float iA0 = rsqrtf(fmaxf(a0, 1e-24f));   // matches v/max(||v||,1e-12)
    float iA1 = rsqrtf(fmaxf(a1, 1e-24f));
    float iB0 = rsqrtf(fmaxf(b0, 1e-24f));
    float iB1 = rsqrtf(fmaxf(b1, 1e-24f));

    // Layer 1 on UNNORMALIZED diffs (overlaps the MUFU rsqrt); constants
    // shared between pairs A and B by CSE.
    u64 uA0 = dfma(dzA, c_w[2],  dfma(dyA, c_w[1],  dmul(dxA, c_w[0])));
    u64 uB0 = dfma(dzB, c_w[2],  dfma(dyB, c_w[1],  dmul(dxB, c_w[0])));
    u64 uA1 = dfma(dzA, c_w[5],  dfma(dyA, c_w[4],  dmul(dxA, c_w[3])));
    u64 uB1 = dfma(dzB, c_w[5],  dfma(dyB, c_w[4],  dmul(dxB, c_w[3])));
    u64 uA2 = dfma(dzA, c_w[8],  dfma(dyA, c_w[7],  dmul(dxA, c_w[6])));
    u64 uB2 = dfma(dzB, c_w[8],  dfma(dyB, c_w[7],  dmul(dxB, c_w[6])));
    u64 uA3 = dfma(dzA, c_w[11], dfma(dyA, c_w[10], dmul(dxA, c_w[9])));
    u64 uB3 = dfma(dzB, c_w[11], dfma(dyB, c_w[10], dmul(dxB, c_w[9])));
    u64 uA4 = dfma(dzA, c_w[14], dfma(dyA, c_w[13], dmul(dxA, c_w[12])));
    u64 uB4 = dfma(dzB, c_w[14], dfma(dyB, c_w[13], dmul(dxB, c_w[12])));

    u64 invA = pk2(iA0, iA1);
    u64 invB = pk2(iB0, iB1);

    u64 hA0 = drelu2(dfma(uA0, invA, c_w[15])), hB0 = drelu2(dfma(uB0, invB, c_w[15]));
    u64 hA1 = drelu2(dfma(uA1, invA, c_w[16])), hB1 = drelu2(dfma(uB1, invB, c_w[16]));
    u64 hA2 = drelu2(dfma(uA2, invA, c_w[17])), hB2 = drelu2(dfma(uB2, invB, c_w[17]));
    u64 hA3 = drelu2(dfma(uA3, invA, c_w[18])), hB3 = drelu2(dfma(uB3, invB, c_w[18]));
    u64 hA4 = drelu2(dfma(uA4, invA, c_w[19])), hB4 = drelu2(dfma(uB4, invB, c_w[19]));

    // Layer 2 (weights pre-scaled by 0.5)
    u64 gA0, gA1, gA2, gA3, gA4, gB0, gB1, gB2, gB3, gB4;
#define L2ROW(GA, GB, J)                                                        \
    GA = dfma(hA0, c_w[20 + 5*(J)], c_w[45 + (J)]);                             \
    GA = dfma(hA1, c_w[21 + 5*(J)], GA); GA = dfma(hA2, c_w[22 + 5*(J)], GA);   \
    GA = dfma(hA3, c_w[23 + 5*(J)], GA); GA = dfma(hA4, c_w[24 + 5*(J)], GA);   \
    GA = drelu2(GA);                                                            \
    GB = dfma(hB0, c_w[20 + 5*(J)], c_w[45 + (J)]);                             \
    GB = dfma(hB1, c_w[21 + 5*(J)], GB); GB = dfma(hB2, c_w[22 + 5*(J)], GB);   \
    GB = dfma(hB3, c_w[23 + 5*(J)], GB); GB = dfma(hB4, c_w[24 + 5*(J)], GB);   \
    GB = drelu2(GB);
    L2ROW(gA0, gB0, 0) L2ROW(gA1, gB1, 1) L2ROW(gA2, gB2, 2)
    L2ROW(gA3, gB3, 3) L2ROW(gA4, gB4, 4)
#undef L2ROW

    // Layer 3 (pre-scaled by 0.5)
    u64 wgA = dfma(gA0, c_w[50], c_w[55]);
    wgA = dfma(gA1, c_w[51], wgA); wgA = dfma(gA2, c_w[52], wgA);
    wgA = dfma(gA3, c_w[53], wgA); wgA = dfma(gA4, c_w[54], wgA);
    u64 wgB = dfma(gB0, c_w[50], c_w[55]);
    wgB = dfma(gB1, c_w[51], wgB); wgB = dfma(gB2, c_w[52], wgB);
    wgB = dfma(gB3, c_w[53], wgB); wgB = dfma(gB4, c_w[54], wgB);

    // vel contribution: d * (inv * w)
    u64 wiA = dmul(wgA, invA);
    u64 wiB = dmul(wgB, invB);
    u64 vx = dmul(dxA, wiA), vy = dmul(dyA, wiA), vz = dmul(dzA, wiA);
    vx = dfma(dxB, wiB, vx); vy = dfma(dyB, wiB, vy); vz = dfma(dzB, wiB, vz);

    // collapse packed halves, then reduce across the 8-lane cluster
    float x0, x1, y0, y1, z0, z1;
    upk(vx, x0, x1); upk(vy, y0, y1); upk(vz, z0, z1);
    float fx = x0 + x1, fy = y0 + y1, fz = z0 + z1;
    fx += __shfl_xor_sync(0xFFFFFFFFu, fx, 1);
    fy += __shfl_xor_sync(0xFFFFFFFFu, fy, 1);
    fz += __shfl_xor_sync(0xFFFFFFFFu, fz, 1);
    fx += __shfl_xor_sync(0xFFFFFFFFu, fx, 2);
    fy += __shfl_xor_sync(0xFFFFFFFFu, fy, 2);
    fz += __shfl_xor_sync(0xFFFFFFFFu, fz, 2);
    fx += __shfl_xor_sync(0xFFFFFFFFu, fx, 4);
    fy += __shfl_xor_sync(0xFFFFFFFFu, fy, 4);
    fz += __shfl_xor_sync(0xFFFFFFFFu, fz, 4);

    if (j == 0 && act) {
        float d2 = fmaf(fx, fx, fmaf(fy, fy, fz * fz));
        d2 = fmaxf(d2, 1e-24f);
        float r = rsqrtf(d2);
        r = r * fmaf(-0.5f * d2 * r, r, 1.5f);  // one Newton step
        out[3 * n + 0] = fx * r;
        out[3 * n + 1] = fy * r;
        out[3 * n + 2] = fz * r;
    }
}

extern "C" void kernel_launch(void* const* d_in, const int* in_sizes, int n_in,
                              void* d_out, int out_size)
{
    const float* pos = (const float*)d_in[0];
    const float* nbr = (const float*)d_in[1];
    const float* W1  = (const float*)d_in[2];
    const float* b1  = (const float*)d_in[3];
    const float* W2  = (const float*)d_in[4];
    const float* b2  = (const float*)d_in[5];
    const float* W3  = (const float*)d_in[6];
    const float* b3  = (const float*)d_in[7];
    float* out = (float*)d_out;

    // 1) pack + pre-scale weights into a __device__ buffer
    pack_weights_kernel<<<1, 64>>>(W1, b1, W2, b2, W3, b3);

    // 2) D2D async copy into the constant bank (graph-capturable memcpy node)
    void* src = nullptr;
    cudaGetSymbolAddress(&src, g_pack);
    cudaMemcpyToSymbolAsync(c_w, src, 60 * sizeof(u64), 0,
                            cudaMemcpyDeviceToDevice, 0);

    // 3) main kernel: one warp per 4 points, 8 lanes per point
    int N = in_sizes[0] / 3;                 // positions is [N,3]
    long long groups = (N + 3) / 4;          // 4 points per warp
    long long warps = groups;
    int threads = 128;
    long long blocks = (warps * 32 + threads - 1) / threads;
    velvec_kernel<<<(int)blocks, threads>>>(pos, nbr, out, N);
}

// round 13
// speedup vs baseline: 1.3103x; 1.0435x over previous
#include <cuda_runtime.h>
#include <cstdint>

typedef unsigned long long u64;

// Packed (v,v) pre-scaled weights in the constant bank as 16B pairs -> LDC.128.
// Pair layout (ulonglong2 index):
//  [2j]    = (W1[j,0], W1[j,1])      j=0..4
//  [2j+1]  = (W1[j,2], b1[j])
//  [10+3j] = (.5W2[j,0], .5W2[j,1])  j=0..4
//  [11+3j] = (.5W2[j,2], .5W2[j,3])
//  [12+3j] = (.5W2[j,4], b2[j])
//  [25]    = (.5W3[0], .5W3[1])
//  [26]    = (.5W3[2], .5W3[3])
//  [27]    = (.5W3[4], b3)
__constant__ __align__(16) ulonglong2 c2[28];
__device__ __align__(16) u64 g_pack[56];

__global__ void pack_weights_kernel(const float* __restrict__ W1, const float* __restrict__ b1,
                                    const float* __restrict__ W2, const float* __restrict__ b2,
                                    const float* __restrict__ W3, const float* __restrict__ b3)
{
    int i = threadIdx.x;
    if (i >= 56) return;
    float v = 0.0f;
    if (i < 20) {                       // L1 pairs: u64 index 4j..4j+3
        int j = i >> 2, r = i & 3;
        v = (r < 3) ? W1[3 * j + r] : b1[j];
    } else if (i < 50) {                // L2: u64 index 20+6j .. 25+6j
        int t = i - 20, j = t / 6, r = t - 6 * j;
        v = (r < 5) ? 0.5f * W2[5 * j + r] : b2[j];
    } else if (i < 55) {
        v = 0.5f * W3[i - 50];
    } else {
        v = b3[0];
    }
    unsigned int u = __float_as_uint(v);
    g_pack[i] = ((u64)u << 32) | (u64)u;
}

// ---------- packed f32x2 helpers ----------
__device__ __forceinline__ u64 pk2(float lo, float hi) {
    u64 r;
    asm("mov.b64 %0, {%1, %2};" : "=l"(r)
        : "r"(__float_as_uint(lo)), "r"(__float_as_uint(hi)));
    return r;
}
__device__ __forceinline__ void upk(u64 a, float& lo, float& hi) {
    unsigned int l_, h_;
    asm("mov.b64 {%0, %1}, %2;" : "=r"(l_), "=r"(h_) : "l"(a));
    lo = __uint_as_float(l_);
    hi = __uint_as_float(h_);
}
__device__ __forceinline__ u64 dfma(u64 a, u64 b, u64 c) {
    u64 d;
    asm("fma.rn.f32x2 %0, %1, %2, %3;" : "=l"(d) : "l"(a), "l"(b), "l"(c));
    return d;
}
__device__ __forceinline__ u64 dmul(u64 a, u64 b) {
    u64 d;
    asm("mul.rn.f32x2 %0, %1, %2;" : "=l"(d) : "l"(a), "l"(b));
    return d;
}
__device__ __forceinline__ u64 dadd(u64 a, u64 b) {
    u64 d;
    asm("add.rn.f32x2 %0, %1, %2;" : "=l"(d) : "l"(a), "l"(b));
    return d;
}
// 2*relu(x) per half, exact: x + |x| (2x folded into pre-halved W2/W3)
__device__ __forceinline__ u64 drelu2(u64 a) {
    return dadd(a, a & 0x7FFFFFFF7FFFFFFFULL);
}

// One warp = 4 points; 8 lanes per point; each lane loads its own contiguous
// 48B (4 neighbors = 2 packed pairs) and runs ONE dual step. Constants read
// as 16B pairs (LDC.128) -> half the const-port pressure of R12.
__global__ void __launch_bounds__(128)
velvec_kernel(const float* __restrict__ pos, const float* __restrict__ nbr,
              float* __restrict__ out, int N)
{
    int gw = (blockIdx.x * blockDim.x + threadIdx.x) >> 5;  // global warp id
    int l = threadIdx.x & 31;
    int p = l >> 3;            // point within warp's group of 4
    int j = l & 7;             // 48B slice within the point's 384B row
    int n = gw * 4 + p;        // global point index
    int nc = (n < N) ? n : (N - 1);   // clamped for loads; store predicated

    // ---- load this lane's 4 neighbors (3x LDG.128, contiguous 48B) ----
    const float4* bp = reinterpret_cast<const float4*>(
        (const char*)nbr + (size_t)nc * 384 + (size_t)j * 48);
    float4 q0 = __ldg(bp + 0);    // x0 y0 z0 x1
    float4 q1 = __ldg(bp + 1);    // y1 z1 x2 y2
    float4 q2 = __ldg(bp + 2);    // z2 x3 y3 z3

    float px = __ldg(pos + 3 * nc + 0);
    float py = __ldg(pos + 3 * nc + 1);
    float pz = __ldg(pos + 3 * nc + 2);
    u64 npx = pk2(-px, -px), npy = pk2(-py, -py), npz = pk2(-pz, -pz);

    // pair A = neighbors 0,1 of the slice; pair B = neighbors 2,3
    u64 axA = pk2(q0.x, q0.w), ayA = pk2(q0.y, q1.x), azA = pk2(q0.z, q1.y);
    u64 axB = pk2(q1.z, q2.y), ayB = pk2(q1.w, q2.z), azB = pk2(q2.x, q2.w);

    u64 dxA = dadd(axA, npx), dyA = dadd(ayA, npy), dzA = dadd(azA, npz);
    u64 dxB = dadd(axB, npx), dyB = dadd(ayB, npy), dzB = dadd(azB, npz);
    u64 d2A = dfma(dxA, dxA, dfma(dyA, dyA, dmul(dzA, dzA)));
    u64 d2B = dfma(dxB, dxB, dfma(dyB, dyB, dmul(dzB, dzB)));
    float a0, a1, b0, b1;
    upk(d2A, a0, a1); upk(d2B, b0, b1);
    float iA0 = rsqrtf(fmaxf(a0, 1e-24f));   // matches v/max(||v||,1e-12)
    float iA1 = rsqrtf(fmaxf(a1, 1e-24f));
    float iB0 = rsqrtf(fmaxf(b0, 1e-24f));
    float iB1 = rsqrtf(fmaxf(b1, 1e-24f));

    // Layer 1 on UNNORMALIZED diffs (overlaps the MUFU rsqrt).
    // Each row j: two LDC.128 pairs.
    u64 uA0, uA1, uA2, uA3, uA4, uB0, uB1, uB2, uB3, uB4;
    u64 B0, B1, B2, B3, B4;
#define L1ROW(UA, UB, BB, J)                                                \
    {                                                                       \
        ulonglong2 t0 = c2[2 * (J)];                                        \
        ulonglong2 t1 = c2[2 * (J) + 1];                                    \
        UA = dfma(dzA, t1.x, dfma(dyA, t0.y, dmul(dxA, t0.x)));             \
        UB = dfma(dzB, t1.x, dfma(dyB, t0.y, dmul(dxB, t0.x)));             \
        BB = t1.y;                                                          \
    }
    L1ROW(uA0, uB0, B0, 0) L1ROW(uA1, uB1, B1, 1) L1ROW(uA2, uB2, B2, 2)
    L1ROW(uA3, uB3, B3, 3) L1ROW(uA4, uB4, B4, 4)
#undef L1ROW

    u64 invA = pk2(iA0, iA1);
    u64 invB = pk2(iB0, iB1);

    u64 hA0 = drelu2(dfma(uA0, invA, B0)), hB0 = drelu2(dfma(uB0, invB, B0));
    u64 hA1 = drelu2(dfma(uA1, invA, B1)), hB1 = drelu2(dfma(uB1, invB, B1));
    u64 hA2 = drelu2(dfma(uA2, invA, B2)), hB2 = drelu2(dfma(uB2, invB, B2));
    u64 hA3 = drelu2(dfma(uA3, invA, B3)), hB3 = drelu2(dfma(uB3, invB, B3));
    u64 hA4 = drelu2(dfma(uA4, invA, B4)), hB4 = drelu2(dfma(uB4, invB, B4));

    // Layer 2 (weights pre-scaled by 0.5): 3 LDC.128 per row
    u64 gA0, gA1, gA2, gA3, gA4, gB0, gB1, gB2, gB3, gB4;
#define L2ROW(GA, GB, J)                                                    \
    {                                                                       \
        ulonglong2 p0 = c2[10 + 3 * (J)];                                   \
        ulonglong2 p1 = c2[11 + 3 * (J)];                                   \
        ulonglong2 p2 = c2[12 + 3 * (J)];                                   \
        GA = dfma(hA0, p0.x, p2.y); GA = dfma(hA1, p0.y, GA);               \
        GA = dfma(hA2, p1.x, GA);   GA = dfma(hA3, p1.y, GA);               \
        GA = dfma(hA4, p2.x, GA);   GA = drelu2(GA);                        \
        GB = dfma(hB0, p0.x, p2.y); GB = dfma(hB1, p0.y, GB);               \
        GB = dfma(hB2, p1.x, GB);   GB = dfma(hB3, p1.y, GB);               \
        GB = dfma(hB4, p2.x, GB);   GB = drelu2(GB);                        \
    }
    L2ROW(gA0, gB0, 0) L2ROW(gA1, gB1, 1) L2ROW(gA2, gB2, 2)
    L2ROW(gA3, gB3, 3) L2ROW(gA4, gB4, 4)
#undef L2ROW

    // Layer 3 (pre-scaled by 0.5): 3 LDC.128
    ulonglong2 q0p = c2[25], q1p = c2[26], q2p = c2[27];
    u64 wgA = dfma(gA0, q0p.x, q2p.y);
    wgA = dfma(gA1, q0p.y, wgA); wgA = dfma(gA2, q1p.x, wgA);
    wgA = dfma(gA3, q1p.y, wgA); wgA = dfma(gA4, q2p.x, wgA);
    u64 wgB = dfma(gB0, q0p.x, q2p.y);
    wgB = dfma(gB1, q0p.y, wgB); wgB = dfma(gB2, q1p.x, wgB);
    wgB = dfma(gB3, q1p.y, wgB); wgB = dfma(gB4, q2p.x, wgB);

    // vel contribution: d * (inv * w)
    u64 wiA = dmul(wgA, invA);
    u64 wiB = dmul(wgB, invB);
    u64 vx = dmul(dxA, wiA), vy = dmul(dyA, wiA), vz = dmul(dzA, wiA);
    vx = dfma(dxB, wiB, vx); vy = dfma(dyB, wiB, vy); vz = dfma(dzB, wiB, vz);

    // collapse packed halves, then reduce across the 8-lane cluster
    float x0, x1, y0, y1, z0, z1;
    upk(vx, x0, x1); upk(vy, y0, y1); upk(vz, z0, z1);
    float fx = x0 + x1, fy = y0 + y1, fz = z0 + z1;
    fx += __shfl_xor_sync(0xFFFFFFFFu, fx, 1);
    fy += __shfl_xor_sync(0xFFFFFFFFu, fy, 1);
    fz += __shfl_xor_sync(0xFFFFFFFFu, fz, 1);
    fx += __shfl_xor_sync(0xFFFFFFFFu, fx, 2);
    fy += __shfl_xor_sync(0xFFFFFFFFu, fy, 2);
    fz += __shfl_xor_sync(0xFFFFFFFFu, fz, 2);
    fx += __shfl_xor_sync(0xFFFFFFFFu, fx, 4);
    fy += __shfl_xor_sync(0xFFFFFFFFu, fy, 4);
    fz += __shfl_xor_sync(0xFFFFFFFFu, fz, 4);

    if (j == 0 && n < N) {
        float d2 = fmaf(fx, fx, fmaf(fy, fy, fz * fz));
        d2 = fmaxf(d2, 1e-24f);
        float r = rsqrtf(d2);
        r = r * fmaf(-0.5f * d2 * r, r, 1.5f);  // one Newton step
        out[3 * n + 0] = fx * r;
        out[3 * n + 1] = fy * r;
        out[3 * n + 2] = fz * r;
    }
}

extern "C" void kernel_launch(void* const* d_in, const int* in_sizes, int n_in,
                              void* d_out, int out_size)
{
    const float* pos = (const float*)d_in[0];
    const float* nbr = (const float*)d_in[1];
    const float* W1  = (const float*)d_in[2];
    const float* b1  = (const float*)d_in[3];
    const float* W2  = (const float*)d_in[4];
    const float* b2  = (const float*)d_in[5];
    const float* W3  = (const float*)d_in[6];
    const float* b3  = (const float*)d_in[7];
    float* out = (float*)d_out;

    // 1) pack + pre-scale weights into a __device__ buffer (paired order)
    pack_weights_kernel<<<1, 64>>>(W1, b1, W2, b2, W3, b3);

    // 2) D2D async copy into the constant bank (graph-capturable memcpy node)
    void* src = nullptr;
    cudaGetSymbolAddress(&src, g_pack);
    cudaMemcpyToSymbolAsync(c2, src, 56 * sizeof(u64), 0,
                            cudaMemcpyDeviceToDevice, 0);

    // 3) main kernel: one warp per 4 points, 8 lanes per point
    int N = in_sizes[0] / 3;                 // positions is [N,3]
    long long warps = (N + 3) / 4;           // 4 points per warp
    int threads = 128;
    long long blocks = (warps * 32 + threads - 1) / threads;
    velvec_kernel<<<(int)blocks, threads>>>(pos, nbr, out, N);
}